// round 7
// baseline (speedup 1.0000x reference)
#include <cuda_runtime.h>
#include <cuda_bf16.h>
#include <math.h>

// Problem constants (fixed by the reference)
#define MAXN 100000
#define MAXE 1600000
#define IN_DIM 128
#define OUT_DIM 64
#define EDGE_DIM 32
#define NHEAD 4
#define HEADD 16

// Scratch (static device globals; no dynamic allocation allowed)
__device__ float g_feat_src[(size_t)MAXN * OUT_DIM];   // 25.6 MB
__device__ float g_feat_dst[(size_t)MAXN * OUT_DIM];   // 25.6 MB
__device__ float g_ex[(size_t)MAXE * NHEAD];           // 25.6 MB exp(logit)
__device__ int   g_deg[MAXN];
__device__ int   g_cursor[MAXN];
__device__ int   g_off[MAXN + 1];
__device__ int   g_bsum[512];
__device__ int   g_eid[MAXE];                          // 6.4 MB CSR edge ids

// ---------------------------------------------------------------------------
// CSR build: zero -> degree histogram -> 2-level exclusive scan -> scatter
// ---------------------------------------------------------------------------
__global__ void k_zero(int N) {
    int i = blockIdx.x * blockDim.x + threadIdx.x;
    if (i < N) { g_deg[i] = 0; g_cursor[i] = 0; }
}

__global__ void k_deg(const int* __restrict__ dst, int E) {
    int e = blockIdx.x * blockDim.x + threadIdx.x;
    if (e < E) atomicAdd(&g_deg[dst[e]], 1);
}

__global__ void k_scan_part(int N) {
    __shared__ int s[256];
    int i = blockIdx.x * 256 + threadIdx.x;
    int v = (i < N) ? g_deg[i] : 0;
    s[threadIdx.x] = v;
    __syncthreads();
#pragma unroll
    for (int off = 1; off < 256; off <<= 1) {
        int t = (threadIdx.x >= off) ? s[threadIdx.x - off] : 0;
        __syncthreads();
        s[threadIdx.x] += t;
        __syncthreads();
    }
    if (i < N) g_off[i] = s[threadIdx.x] - v;       // block-local exclusive
    if (threadIdx.x == 255) g_bsum[blockIdx.x] = s[255];
}

__global__ void k_scan_bsum(int nb) {
    __shared__ int s[512];
    int i = threadIdx.x;
    int v = (i < nb) ? g_bsum[i] : 0;
    s[i] = v;
    __syncthreads();
#pragma unroll
    for (int off = 1; off < 512; off <<= 1) {
        int t = (i >= off) ? s[i - off] : 0;
        __syncthreads();
        s[i] += t;
        __syncthreads();
    }
    if (i < nb) g_bsum[i] = s[i] - v;               // exclusive block offsets
}

__global__ void k_scan_add(int N, int E) {
    int i = blockIdx.x * blockDim.x + threadIdx.x;
    if (i < N) g_off[i] += g_bsum[i >> 8];
    if (i == 0) g_off[N] = E;
}

__global__ void k_scatter(const int* __restrict__ dst, int E) {
    int e = blockIdx.x * blockDim.x + threadIdx.x;
    if (e < E) {
        int d = dst[e];
        int p = atomicAdd(&g_cursor[d], 1);
        g_eid[g_off[d] + p] = e;
    }
}

// ---------------------------------------------------------------------------
// Kernel 1 (fused): both node projections as one register-tiled GEMM.
//   C[n, j] = sum_k nf[n,k] * Wcat[j,k],  j in [0,128): j<64 -> W_src, else W_dst
// Block tile: 64 nodes x 128 outputs. 256 threads, each an 8x4 register tile.
// ---------------------------------------------------------------------------
#define WS_PITCH 132
#define PROJ_SMEM_BYTES (IN_DIM * WS_PITCH * 4 + 64 * IN_DIM * 4)

__global__ void __launch_bounds__(256, 2)
k_node_proj_fused(const float* __restrict__ nf,
                  const float* __restrict__ W_src,
                  const float* __restrict__ W_dst,
                  int N) {
    extern __shared__ float sm[];
    float* Ws  = sm;                          // [128][WS_PITCH]
    float* nds = sm + IN_DIM * WS_PITCH;      // [64][128]

    int t = threadIdx.x;

    for (int i = t; i < 128 * (IN_DIM / 4); i += 256) {
        int j  = i >> 5;
        int k4 = i & 31;
        float4 w = (j < 64)
            ? ((const float4*)W_src)[(size_t)j * (IN_DIM / 4) + k4]
            : ((const float4*)W_dst)[(size_t)(j - 64) * (IN_DIM / 4) + k4];
        int k = k4 * 4;
        Ws[(k + 0) * WS_PITCH + j] = w.x;
        Ws[(k + 1) * WS_PITCH + j] = w.y;
        Ws[(k + 2) * WS_PITCH + j] = w.z;
        Ws[(k + 3) * WS_PITCH + j] = w.w;
    }
    __syncthreads();

    int tx = t & 31;
    int ty = t >> 5;
    int node_base_l = ty * 8;

    int ntiles = (N + 63) >> 6;
    for (int tile = blockIdx.x; tile < ntiles; tile += gridDim.x) {
        int node0 = tile * 64;

        for (int i = t; i < 64 * (IN_DIM / 4); i += 256) {
            int row = i >> 5;
            int k4  = i & 31;
            int node = node0 + row;
            float4 v = make_float4(0.f, 0.f, 0.f, 0.f);
            if (node < N)
                v = ((const float4*)nf)[(size_t)node * (IN_DIM / 4) + k4];
            ((float4*)(nds + row * IN_DIM))[k4] = v;
        }
        __syncthreads();

        float acc[8][4];
#pragma unroll
        for (int i = 0; i < 8; i++)
#pragma unroll
            for (int c = 0; c < 4; c++) acc[i][c] = 0.0f;

        const float* a0 = nds + node_base_l * IN_DIM;
#pragma unroll 2
        for (int k4 = 0; k4 < IN_DIM / 4; k4++) {
            float4 a4[8];
#pragma unroll
            for (int i = 0; i < 8; i++)
                a4[i] = *(const float4*)(a0 + i * IN_DIM + 4 * k4);
#pragma unroll
            for (int c = 0; c < 4; c++) {
                float4 b = *(const float4*)(Ws + (4 * k4 + c) * WS_PITCH + 4 * tx);
#pragma unroll
                for (int i = 0; i < 8; i++) {
                    float av = (c == 0) ? a4[i].x : (c == 1) ? a4[i].y
                             : (c == 2) ? a4[i].z : a4[i].w;
                    acc[i][0] += av * b.x;
                    acc[i][1] += av * b.y;
                    acc[i][2] += av * b.z;
                    acc[i][3] += av * b.w;
                }
            }
        }

        {
            float* outbase = (tx < 16) ? g_feat_src : g_feat_dst;
            int jq = (tx < 16) ? tx : (tx - 16);
#pragma unroll
            for (int i = 0; i < 8; i++) {
                int node = node0 + node_base_l + i;
                if (node < N) {
                    float4 v = make_float4(acc[i][0], acc[i][1], acc[i][2], acc[i][3]);
                    ((float4*)(outbase + (size_t)node * OUT_DIM))[jq] = v;
                }
            }
        }
        __syncthreads();
    }
}

// ---------------------------------------------------------------------------
// Kernel 2: per-edge GATv2 logits + exp (no atomics; CSR pass sums ex later)
// Thread = (edge-pair, head): edges (le, le+64) of a 128-edge tile.
// ---------------------------------------------------------------------------
__global__ void __launch_bounds__(256)
k_edge_logits(const float* __restrict__ ef,
              const float* __restrict__ W_edge,
              const float* __restrict__ attn,
              const int* __restrict__ src,
              const int* __restrict__ dst,
              int E) {
    __shared__ float4 WeT4[EDGE_DIM * (OUT_DIM / 4)];   // [k][j4], 8 KB
    __shared__ float  attn_s[NHEAD * HEADD];            // 256 B
    __shared__ float4 efs[128][EDGE_DIM / 4];           // 16 KB
    __shared__ int    sidx[128], didx[128];

    for (int i = threadIdx.x; i < EDGE_DIM * OUT_DIM; i += blockDim.x) {
        int k = i >> 6;
        int j = i & 63;
        ((float*)WeT4)[i] = W_edge[(size_t)j * EDGE_DIM + k];
    }
    if (threadIdx.x < NHEAD * HEADD) attn_s[threadIdx.x] = attn[threadIdx.x];
    __syncthreads();

    int t = threadIdx.x;
    int le = t >> 2;
    int h  = t & 3;

    int egroups = (E + 127) >> 7;
    for (int g = blockIdx.x; g < egroups; g += gridDim.x) {
        int ebase = g * 128;
        for (int i = t; i < 128 * (EDGE_DIM / 4); i += blockDim.x) {
            int lee = i >> 3;
            int k4  = i & 7;
            int e = ebase + lee;
            if (e < E)
                efs[lee][k4] = ((const float4*)ef)[(size_t)e * (EDGE_DIM / 4) + k4];
        }
        if (t < 128 && ebase + t < E) {
            sidx[t] = src[ebase + t];
            didx[t] = dst[ebase + t];
        }
        __syncthreads();

        int eA = ebase + le;
        int eB = eA + 64;
        bool vA = eA < E;
        bool vB = eB < E;
        int sA = vA ? sidx[le] : 0,      dA = vA ? didx[le] : 0;
        int sB = vB ? sidx[le + 64] : 0, dB = vB ? didx[le + 64] : 0;

        float4 A0, A1, A2, A3, B0, B1, B2, B3;
        {
            const float4* fsA = (const float4*)g_feat_src + (size_t)sA * (OUT_DIM / 4) + h * 4;
            const float4* fdA = (const float4*)g_feat_dst + (size_t)dA * (OUT_DIM / 4) + h * 4;
            const float4* fsB = (const float4*)g_feat_src + (size_t)sB * (OUT_DIM / 4) + h * 4;
            const float4* fdB = (const float4*)g_feat_dst + (size_t)dB * (OUT_DIM / 4) + h * 4;
            float4 x, y;
            x = fsA[0]; y = fdA[0]; A0 = make_float4(x.x + y.x, x.y + y.y, x.z + y.z, x.w + y.w);
            x = fsA[1]; y = fdA[1]; A1 = make_float4(x.x + y.x, x.y + y.y, x.z + y.z, x.w + y.w);
            x = fsA[2]; y = fdA[2]; A2 = make_float4(x.x + y.x, x.y + y.y, x.z + y.z, x.w + y.w);
            x = fsA[3]; y = fdA[3]; A3 = make_float4(x.x + y.x, x.y + y.y, x.z + y.z, x.w + y.w);
            x = fsB[0]; y = fdB[0]; B0 = make_float4(x.x + y.x, x.y + y.y, x.z + y.z, x.w + y.w);
            x = fsB[1]; y = fdB[1]; B1 = make_float4(x.x + y.x, x.y + y.y, x.z + y.z, x.w + y.w);
            x = fsB[2]; y = fdB[2]; B2 = make_float4(x.x + y.x, x.y + y.y, x.z + y.z, x.w + y.w);
            x = fsB[3]; y = fdB[3]; B3 = make_float4(x.x + y.x, x.y + y.y, x.z + y.z, x.w + y.w);
        }

        const float4* wrow = WeT4 + h * 4;
#pragma unroll
        for (int k4 = 0; k4 < EDGE_DIM / 4; k4++) {
            float4 evA = efs[le][k4];
            float4 evB = efs[le + 64][k4];
#define EDGE_MAC2(compA, compB, kk)                                      \
            {                                                            \
                float va = compA, vb = compB;                            \
                float4 w0 = wrow[(kk) * 16 + 0];                         \
                float4 w1 = wrow[(kk) * 16 + 1];                         \
                float4 w2 = wrow[(kk) * 16 + 2];                         \
                float4 w3 = wrow[(kk) * 16 + 3];                         \
                A0.x += va * w0.x; A0.y += va * w0.y; A0.z += va * w0.z; A0.w += va * w0.w; \
                A1.x += va * w1.x; A1.y += va * w1.y; A1.z += va * w1.z; A1.w += va * w1.w; \
                A2.x += va * w2.x; A2.y += va * w2.y; A2.z += va * w2.z; A2.w += va * w2.w; \
                A3.x += va * w3.x; A3.y += va * w3.y; A3.z += va * w3.z; A3.w += va * w3.w; \
                B0.x += vb * w0.x; B0.y += vb * w0.y; B0.z += vb * w0.z; B0.w += vb * w0.w; \
                B1.x += vb * w1.x; B1.y += vb * w1.y; B1.z += vb * w1.z; B1.w += vb * w1.w; \
                B2.x += vb * w2.x; B2.y += vb * w2.y; B2.z += vb * w2.z; B2.w += vb * w2.w; \
                B3.x += vb * w3.x; B3.y += vb * w3.y; B3.z += vb * w3.z; B3.w += vb * w3.w; \
            }
            EDGE_MAC2(evA.x, evB.x, k4 * 4 + 0)
            EDGE_MAC2(evA.y, evB.y, k4 * 4 + 1)
            EDGE_MAC2(evA.z, evB.z, k4 * 4 + 2)
            EDGE_MAC2(evA.w, evB.w, k4 * 4 + 3)
#undef EDGE_MAC2
        }

        const float* lh = attn_s + h * HEADD;
        float logitA = 0.0f, logitB = 0.0f;
#define LK(lg, av, idx0)                                                 \
        lg += fmaxf(av.x, 0.2f * av.x) * lh[(idx0) + 0];                 \
        lg += fmaxf(av.y, 0.2f * av.y) * lh[(idx0) + 1];                 \
        lg += fmaxf(av.z, 0.2f * av.z) * lh[(idx0) + 2];                 \
        lg += fmaxf(av.w, 0.2f * av.w) * lh[(idx0) + 3];
        LK(logitA, A0, 0) LK(logitA, A1, 4) LK(logitA, A2, 8) LK(logitA, A3, 12)
        LK(logitB, B0, 0) LK(logitB, B1, 4) LK(logitB, B2, 8) LK(logitB, B3, 12)
#undef LK

        // exp without max-shift: alpha identical, fp32-safe (|logit| < ~35)
        if (vA) g_ex[(size_t)eA * NHEAD + h] = __expf(logitA);
        if (vB) g_ex[(size_t)eB * NHEAD + h] = __expf(logitB);
        __syncthreads();
    }
}

// ---------------------------------------------------------------------------
// Kernel 3: pull-based aggregation, warp per node. No atomics.
// Phase 1: lanes sum ex4 over the node's CSR edge list; butterfly reduce.
// Phase 2: lane-cooperative edge loop; lane owns 2 output dims; writes alpha.
// ---------------------------------------------------------------------------
__global__ void __launch_bounds__(256)
k_node_agg(const int* __restrict__ src,
           const float* __restrict__ bias,
           float* __restrict__ rst,
           float* __restrict__ alpha_out,   // may be null
           int N, int E) {
    int node = blockIdx.x * 8 + (threadIdx.x >> 5);
    int lane = threadIdx.x & 31;
    if (node >= N) return;

    int start = g_off[node];
    int end   = g_off[node + 1];

    float2 bias2 = ((const float2*)bias)[lane];

    if (start == end) {   // degree-0 node: rst = bias
        ((float2*)rst)[(size_t)node * (OUT_DIM / 2) + lane] = bias2;
        return;
    }

    // Phase 1: sum of ex over edges, per head
    float4 sum4 = make_float4(0.f, 0.f, 0.f, 0.f);
    for (int j = start + lane; j < end; j += 32) {
        float4 x = ((const float4*)g_ex)[g_eid[j]];
        sum4.x += x.x; sum4.y += x.y; sum4.z += x.z; sum4.w += x.w;
    }
#pragma unroll
    for (int off = 16; off > 0; off >>= 1) {
        sum4.x += __shfl_xor_sync(0xFFFFFFFFu, sum4.x, off);
        sum4.y += __shfl_xor_sync(0xFFFFFFFFu, sum4.y, off);
        sum4.z += __shfl_xor_sync(0xFFFFFFFFu, sum4.z, off);
        sum4.w += __shfl_xor_sync(0xFFFFFFFFu, sum4.w, off);
    }
    float4 inv4 = make_float4(1.f / sum4.x, 1.f / sum4.y, 1.f / sum4.z, 1.f / sum4.w);

    int h = lane >> 3;                     // head owning my 2 dims
    float accx = 0.f, accy = 0.f;

    // Phase 2: lane-cooperative edges, 32 at a time
    for (int j0 = start; j0 < end; j0 += 32) {
        int cnt = min(32, end - j0);
        int mye = (lane < cnt) ? g_eid[j0 + lane] : 0;
        int mys = (lane < cnt) ? src[mye] : 0;
        float4 myal = make_float4(0.f, 0.f, 0.f, 0.f);
        if (lane < cnt) {
            float4 ex4 = ((const float4*)g_ex)[mye];
            myal = make_float4(ex4.x * inv4.x, ex4.y * inv4.y,
                               ex4.z * inv4.z, ex4.w * inv4.w);
            if (alpha_out) ((float4*)alpha_out)[mye] = myal;
        }
        for (int k = 0; k < cnt; k++) {
            int s = __shfl_sync(0xFFFFFFFFu, mys, k);
            float a0 = __shfl_sync(0xFFFFFFFFu, myal.x, k);
            float a1 = __shfl_sync(0xFFFFFFFFu, myal.y, k);
            float a2 = __shfl_sync(0xFFFFFFFFu, myal.z, k);
            float a3 = __shfl_sync(0xFFFFFFFFu, myal.w, k);
            float a = (h == 0) ? a0 : (h == 1) ? a1 : (h == 2) ? a2 : a3;
            float2 v = ((const float2*)g_feat_src)[(size_t)s * (OUT_DIM / 2) + lane];
            accx += v.x * a;
            accy += v.y * a;
        }
    }

    ((float2*)rst)[(size_t)node * (OUT_DIM / 2) + lane] =
        make_float2(accx + bias2.x, accy + bias2.y);
}

// ---------------------------------------------------------------------------
// Launch
// ---------------------------------------------------------------------------
extern "C" void kernel_launch(void* const* d_in, const int* in_sizes, int n_in,
                              void* d_out, int out_size) {
    const float* node_feat = (const float*)d_in[0];
    const float* edge_feat = (const float*)d_in[1];
    const float* W_src     = (const float*)d_in[2];
    const float* W_dst     = (const float*)d_in[3];
    const float* W_edge    = (const float*)d_in[4];
    const float* attn      = (const float*)d_in[5];
    const float* bias      = (const float*)d_in[6];
    const int*   src       = (const int*)d_in[7];
    const int*   dst       = (const int*)d_in[8];

    int N = in_sizes[0] / IN_DIM;
    int E = in_sizes[1] / EDGE_DIM;

    float* rst = (float*)d_out;
    float* alpha_out = nullptr;
    if (out_size >= N * OUT_DIM + E * NHEAD)
        alpha_out = rst + (size_t)N * OUT_DIM;

    int nb = (N + 255) / 256;

    // CSR build chain
    k_zero<<<nb, 256>>>(N);
    k_deg<<<(E + 255) / 256, 256>>>(dst, E);
    k_scan_part<<<nb, 256>>>(N);
    k_scan_bsum<<<1, 512>>>(nb);
    k_scan_add<<<nb, 256>>>(N, E);
    k_scatter<<<(E + 255) / 256, 256>>>(dst, E);

    // Fused dual node projection (dynamic smem > 48KB)
    cudaFuncSetAttribute(k_node_proj_fused,
                         cudaFuncAttributeMaxDynamicSharedMemorySize,
                         PROJ_SMEM_BYTES);
    int ntiles = (N + 63) / 64;
    k_node_proj_fused<<<ntiles, 256, PROJ_SMEM_BYTES>>>(node_feat, W_src, W_dst, N);

    // Edge logits + exp (no atomics)
    k_edge_logits<<<2960, 256>>>(edge_feat, W_edge, attn, src, dst, E);

    // Pull-based aggregation (warp per node)
    k_node_agg<<<(N + 7) / 8, 256>>>(src, bias, rst, alpha_out, N, E);
}

// round 17
// speedup vs baseline: 1.6272x; 1.6272x over previous
#include <cuda_runtime.h>
#include <cuda_bf16.h>
#include <math.h>

// Problem constants (fixed by the reference)
#define MAXN 100000
#define MAXE 1600000
#define IN_DIM 128
#define OUT_DIM 64
#define EDGE_DIM 32
#define NHEAD 4
#define HEADD 16

// Scratch (static device globals; no dynamic allocation allowed)
__device__ float g_feat_src[(size_t)MAXN * OUT_DIM];   // 25.6 MB
__device__ float g_feat_dst[(size_t)MAXN * OUT_DIM];   // 25.6 MB
__device__ float g_ex[(size_t)MAXE * NHEAD];           // 25.6 MB exp(logit)
__device__ float g_seg_sum[(size_t)MAXN * NHEAD];      // 1.6 MB

// ---------------------------------------------------------------------------
// Kernel 0: init rst = bias (broadcast) and seg_sum = 0
// ---------------------------------------------------------------------------
__global__ void k_init(float* __restrict__ rst, const float* __restrict__ bias, int N) {
    int i = blockIdx.x * blockDim.x + threadIdx.x;
    int total = N * OUT_DIM;
    if (i < total) rst[i] = bias[i & (OUT_DIM - 1)];
    if (i < N * NHEAD) g_seg_sum[i] = 0.0f;
}

// ---------------------------------------------------------------------------
// Kernel 1 (fused): both node projections as one register-tiled GEMM.
//   C[n, j] = sum_k nf[n,k] * Wcat[j,k],  j in [0,128): j<64 -> W_src, else W_dst
// Block tile: 64 nodes x 128 outputs. 256 threads, each an 8x4 register tile.
// ---------------------------------------------------------------------------
#define WS_PITCH 132
#define PROJ_SMEM_BYTES (IN_DIM * WS_PITCH * 4 + 64 * IN_DIM * 4)

__global__ void __launch_bounds__(256, 2)
k_node_proj_fused(const float* __restrict__ nf,
                  const float* __restrict__ W_src,
                  const float* __restrict__ W_dst,
                  int N) {
    extern __shared__ float sm[];
    float* Ws  = sm;                          // [128][WS_PITCH]
    float* nds = sm + IN_DIM * WS_PITCH;      // [64][128]

    int t = threadIdx.x;

    for (int i = t; i < 128 * (IN_DIM / 4); i += 256) {
        int j  = i >> 5;
        int k4 = i & 31;
        float4 w = (j < 64)
            ? ((const float4*)W_src)[(size_t)j * (IN_DIM / 4) + k4]
            : ((const float4*)W_dst)[(size_t)(j - 64) * (IN_DIM / 4) + k4];
        int k = k4 * 4;
        Ws[(k + 0) * WS_PITCH + j] = w.x;
        Ws[(k + 1) * WS_PITCH + j] = w.y;
        Ws[(k + 2) * WS_PITCH + j] = w.z;
        Ws[(k + 3) * WS_PITCH + j] = w.w;
    }
    __syncthreads();

    int tx = t & 31;
    int ty = t >> 5;
    int node_base_l = ty * 8;

    int ntiles = (N + 63) >> 6;
    for (int tile = blockIdx.x; tile < ntiles; tile += gridDim.x) {
        int node0 = tile * 64;

        for (int i = t; i < 64 * (IN_DIM / 4); i += 256) {
            int row = i >> 5;
            int k4  = i & 31;
            int node = node0 + row;
            float4 v = make_float4(0.f, 0.f, 0.f, 0.f);
            if (node < N)
                v = ((const float4*)nf)[(size_t)node * (IN_DIM / 4) + k4];
            ((float4*)(nds + row * IN_DIM))[k4] = v;
        }
        __syncthreads();

        float acc[8][4];
#pragma unroll
        for (int i = 0; i < 8; i++)
#pragma unroll
            for (int c = 0; c < 4; c++) acc[i][c] = 0.0f;

        const float* a0 = nds + node_base_l * IN_DIM;
#pragma unroll 2
        for (int k4 = 0; k4 < IN_DIM / 4; k4++) {
            float4 a4[8];
#pragma unroll
            for (int i = 0; i < 8; i++)
                a4[i] = *(const float4*)(a0 + i * IN_DIM + 4 * k4);
#pragma unroll
            for (int c = 0; c < 4; c++) {
                float4 b = *(const float4*)(Ws + (4 * k4 + c) * WS_PITCH + 4 * tx);
#pragma unroll
                for (int i = 0; i < 8; i++) {
                    float av = (c == 0) ? a4[i].x : (c == 1) ? a4[i].y
                             : (c == 2) ? a4[i].z : a4[i].w;
                    acc[i][0] += av * b.x;
                    acc[i][1] += av * b.y;
                    acc[i][2] += av * b.z;
                    acc[i][3] += av * b.w;
                }
            }
        }

        {
            float* outbase = (tx < 16) ? g_feat_src : g_feat_dst;
            int jq = (tx < 16) ? tx : (tx - 16);
#pragma unroll
            for (int i = 0; i < 8; i++) {
                int node = node0 + node_base_l + i;
                if (node < N) {
                    float4 v = make_float4(acc[i][0], acc[i][1], acc[i][2], acc[i][3]);
                    ((float4*)(outbase + (size_t)node * OUT_DIM))[jq] = v;
                }
            }
        }
        __syncthreads();
    }
}

// ---------------------------------------------------------------------------
// Kernel 2: per-edge GATv2 logits + exp + segment-sum (denominator)
// Thread = (edge-pair, head): edges (le, le+64) of a 128-edge tile.
// ---------------------------------------------------------------------------
__global__ void __launch_bounds__(256)
k_edge_logits(const float* __restrict__ ef,
              const float* __restrict__ W_edge,
              const float* __restrict__ attn,
              const int* __restrict__ src,
              const int* __restrict__ dst,
              int E) {
    __shared__ float4 WeT4[EDGE_DIM * (OUT_DIM / 4)];   // [k][j4], 8 KB
    __shared__ float  attn_s[NHEAD * HEADD];            // 256 B
    __shared__ float4 efs[128][EDGE_DIM / 4];           // 16 KB
    __shared__ int    sidx[128], didx[128];

    for (int i = threadIdx.x; i < EDGE_DIM * OUT_DIM; i += blockDim.x) {
        int k = i >> 6;
        int j = i & 63;
        ((float*)WeT4)[i] = W_edge[(size_t)j * EDGE_DIM + k];
    }
    if (threadIdx.x < NHEAD * HEADD) attn_s[threadIdx.x] = attn[threadIdx.x];
    __syncthreads();

    int t = threadIdx.x;
    int le = t >> 2;
    int h  = t & 3;

    int egroups = (E + 127) >> 7;
    for (int g = blockIdx.x; g < egroups; g += gridDim.x) {
        int ebase = g * 128;
        for (int i = t; i < 128 * (EDGE_DIM / 4); i += blockDim.x) {
            int lee = i >> 3;
            int k4  = i & 7;
            int e = ebase + lee;
            if (e < E)
                efs[lee][k4] = ((const float4*)ef)[(size_t)e * (EDGE_DIM / 4) + k4];
        }
        if (t < 128 && ebase + t < E) {
            sidx[t] = src[ebase + t];
            didx[t] = dst[ebase + t];
        }
        __syncthreads();

        int eA = ebase + le;
        int eB = eA + 64;
        bool vA = eA < E;
        bool vB = eB < E;
        int sA = vA ? sidx[le] : 0,      dA = vA ? didx[le] : 0;
        int sB = vB ? sidx[le + 64] : 0, dB = vB ? didx[le + 64] : 0;

        float4 A0, A1, A2, A3, B0, B1, B2, B3;
        {
            const float4* fsA = (const float4*)g_feat_src + (size_t)sA * (OUT_DIM / 4) + h * 4;
            const float4* fdA = (const float4*)g_feat_dst + (size_t)dA * (OUT_DIM / 4) + h * 4;
            const float4* fsB = (const float4*)g_feat_src + (size_t)sB * (OUT_DIM / 4) + h * 4;
            const float4* fdB = (const float4*)g_feat_dst + (size_t)dB * (OUT_DIM / 4) + h * 4;
            float4 x, y;
            x = fsA[0]; y = fdA[0]; A0 = make_float4(x.x + y.x, x.y + y.y, x.z + y.z, x.w + y.w);
            x = fsA[1]; y = fdA[1]; A1 = make_float4(x.x + y.x, x.y + y.y, x.z + y.z, x.w + y.w);
            x = fsA[2]; y = fdA[2]; A2 = make_float4(x.x + y.x, x.y + y.y, x.z + y.z, x.w + y.w);
            x = fsA[3]; y = fdA[3]; A3 = make_float4(x.x + y.x, x.y + y.y, x.z + y.z, x.w + y.w);
            x = fsB[0]; y = fdB[0]; B0 = make_float4(x.x + y.x, x.y + y.y, x.z + y.z, x.w + y.w);
            x = fsB[1]; y = fdB[1]; B1 = make_float4(x.x + y.x, x.y + y.y, x.z + y.z, x.w + y.w);
            x = fsB[2]; y = fdB[2]; B2 = make_float4(x.x + y.x, x.y + y.y, x.z + y.z, x.w + y.w);
            x = fsB[3]; y = fdB[3]; B3 = make_float4(x.x + y.x, x.y + y.y, x.z + y.z, x.w + y.w);
        }

        const float4* wrow = WeT4 + h * 4;
#pragma unroll
        for (int k4 = 0; k4 < EDGE_DIM / 4; k4++) {
            float4 evA = efs[le][k4];
            float4 evB = efs[le + 64][k4];
#define EDGE_MAC2(compA, compB, kk)                                      \
            {                                                            \
                float va = compA, vb = compB;                            \
                float4 w0 = wrow[(kk) * 16 + 0];                         \
                float4 w1 = wrow[(kk) * 16 + 1];                         \
                float4 w2 = wrow[(kk) * 16 + 2];                         \
                float4 w3 = wrow[(kk) * 16 + 3];                         \
                A0.x += va * w0.x; A0.y += va * w0.y; A0.z += va * w0.z; A0.w += va * w0.w; \
                A1.x += va * w1.x; A1.y += va * w1.y; A1.z += va * w1.z; A1.w += va * w1.w; \
                A2.x += va * w2.x; A2.y += va * w2.y; A2.z += va * w2.z; A2.w += va * w2.w; \
                A3.x += va * w3.x; A3.y += va * w3.y; A3.z += va * w3.z; A3.w += va * w3.w; \
                B0.x += vb * w0.x; B0.y += vb * w0.y; B0.z += vb * w0.z; B0.w += vb * w0.w; \
                B1.x += vb * w1.x; B1.y += vb * w1.y; B1.z += vb * w1.z; B1.w += vb * w1.w; \
                B2.x += vb * w2.x; B2.y += vb * w2.y; B2.z += vb * w2.z; B2.w += vb * w2.w; \
                B3.x += vb * w3.x; B3.y += vb * w3.y; B3.z += vb * w3.z; B3.w += vb * w3.w; \
            }
            EDGE_MAC2(evA.x, evB.x, k4 * 4 + 0)
            EDGE_MAC2(evA.y, evB.y, k4 * 4 + 1)
            EDGE_MAC2(evA.z, evB.z, k4 * 4 + 2)
            EDGE_MAC2(evA.w, evB.w, k4 * 4 + 3)
#undef EDGE_MAC2
        }

        const float* lh = attn_s + h * HEADD;
        float logitA = 0.0f, logitB = 0.0f;
#define LK(lg, av, idx0)                                                 \
        lg += fmaxf(av.x, 0.2f * av.x) * lh[(idx0) + 0];                 \
        lg += fmaxf(av.y, 0.2f * av.y) * lh[(idx0) + 1];                 \
        lg += fmaxf(av.z, 0.2f * av.z) * lh[(idx0) + 2];                 \
        lg += fmaxf(av.w, 0.2f * av.w) * lh[(idx0) + 3];
        LK(logitA, A0, 0) LK(logitA, A1, 4) LK(logitA, A2, 8) LK(logitA, A3, 12)
        LK(logitB, B0, 0) LK(logitB, B1, 4) LK(logitB, B2, 8) LK(logitB, B3, 12)
#undef LK

        // exp without max-shift: alpha identical, fp32-safe (|logit| < ~35)
        if (vA) {
            float exl = __expf(logitA);
            g_ex[(size_t)eA * NHEAD + h] = exl;
            atomicAdd(&g_seg_sum[(size_t)dA * NHEAD + h], exl);
        }
        if (vB) {
            float exl = __expf(logitB);
            g_ex[(size_t)eB * NHEAD + h] = exl;
            atomicAdd(&g_seg_sum[(size_t)dB * NHEAD + h], exl);
        }
        __syncthreads();
    }
}

// ---------------------------------------------------------------------------
// Kernel 3: normalize alpha + aggregate, one HALF-WARP (16 lanes) per edge.
// Lane owns 4 contiguous output dims (float4): fs gather and red.v4 are
// fully coalesced (256B per edge) instead of 32-line scatter.
// Grid-stride over edges (16 half-warps per 256-thread block).
// ---------------------------------------------------------------------------
__global__ void __launch_bounds__(256)
k_aggregate(const int* __restrict__ src,
            const int* __restrict__ dst,
            float* __restrict__ rst,
            float* __restrict__ alpha_out,   // may be null
            int E) {
    int hw_global = (blockIdx.x * blockDim.x + threadIdx.x) >> 4;
    int hw_stride = (gridDim.x * blockDim.x) >> 4;
    int lane = threadIdx.x & 15;             // 16 lanes per edge
    int h = lane >> 2;                       // head owning my 4 dims

    for (int e = hw_global; e < E; e += hw_stride) {
        int s = src[e];                       // uniform within half-warp
        int d = dst[e];

        float exh = g_ex[(size_t)e * NHEAD + h];            // broadcast load
        float ssh = g_seg_sum[(size_t)d * NHEAD + h];       // broadcast load
        float a = exh / ssh;
        if (alpha_out && (lane & 3) == 0)
            alpha_out[(size_t)e * NHEAD + h] = a;           // 4 lanes, 1 line

        float4 v = ((const float4*)g_feat_src)[(size_t)s * (OUT_DIM / 4) + lane];
        float* ro = rst + (size_t)d * OUT_DIM + lane * 4;
        asm volatile("red.global.add.v4.f32 [%0], {%1, %2, %3, %4};"
                     :: "l"(ro), "f"(v.x * a), "f"(v.y * a),
                        "f"(v.z * a), "f"(v.w * a) : "memory");
    }
}

// ---------------------------------------------------------------------------
// Launch
// ---------------------------------------------------------------------------
extern "C" void kernel_launch(void* const* d_in, const int* in_sizes, int n_in,
                              void* d_out, int out_size) {
    const float* node_feat = (const float*)d_in[0];
    const float* edge_feat = (const float*)d_in[1];
    const float* W_src     = (const float*)d_in[2];
    const float* W_dst     = (const float*)d_in[3];
    const float* W_edge    = (const float*)d_in[4];
    const float* attn      = (const float*)d_in[5];
    const float* bias      = (const float*)d_in[6];
    const int*   src       = (const int*)d_in[7];
    const int*   dst       = (const int*)d_in[8];

    int N = in_sizes[0] / IN_DIM;
    int E = in_sizes[1] / EDGE_DIM;

    float* rst = (float*)d_out;
    float* alpha_out = nullptr;
    if (out_size >= N * OUT_DIM + E * NHEAD)
        alpha_out = rst + (size_t)N * OUT_DIM;

    // K0: init output + seg_sum
    {
        int total = N * OUT_DIM;
        k_init<<<(total + 255) / 256, 256>>>(rst, bias, N);
    }
    // K1: fused dual node projection (dynamic smem > 48KB)
    {
        cudaFuncSetAttribute(k_node_proj_fused,
                             cudaFuncAttributeMaxDynamicSharedMemorySize,
                             PROJ_SMEM_BYTES);
        int ntiles = (N + 63) / 64;
        k_node_proj_fused<<<ntiles, 256, PROJ_SMEM_BYTES>>>(node_feat, W_src, W_dst, N);
    }
    // K2: edge logits + exp + segment sum
    k_edge_logits<<<2960, 256>>>(edge_feat, W_edge, attn, src, dst, E);
    // K3: normalize + aggregate (half-warp per edge, coalesced, grid-stride)
    k_aggregate<<<4096, 256>>>(src, dst, rst, alpha_out, E);
}